// round 17
// baseline (speedup 1.0000x reference)
#include <cuda_runtime.h>

// Problem constants
#define BB      16
#define TT      1024
#define NK      1024
#define DD      256
#define WIN     64

// Each CTA handles 64 t-rows (two 32-row tiles A/B) against ONE K/V window.
// Shared memory (floats):
//   Qs: 32 x 260 pad-stride                                 8320
//   Ks: 64 x 256 XOR-swizzled (K window, then V window)    16384
//   Ps: 64 x 64  (probs: rows 0-31 tile A, 32-63 tile B)    4096
// Total 28800 floats = 115200 B -> 2 CTAs/SM.
//
// K/V swizzle: 16B chunk d4 of row j lives at chunk (d4 ^ (j & 7)).
#define QS_STRIDE   260
#define KS_STRIDE   256
#define PS_STRIDE   64

#define QS_OFF      0
#define KS_OFF      8320
#define PS_OFF      (KS_OFF + WIN * KS_STRIDE)           // 24704
#define SMEM_FLOATS (PS_OFF + 64 * PS_STRIDE)            // 28800
#define SMEM_BYTES  (SMEM_FLOATS * 4)                    // 115200

// Output layout: R (B,T,512) | alignments (B,N,T) | max_attentions (B,T)
#define R_ELEMS   ((size_t)BB * TT * (2 * DD))           // 8,388,608
#define AL_ELEMS  ((size_t)BB * NK * TT)                 // 16,777,216

typedef unsigned long long u64;
typedef unsigned int       u32;

union UF2 { u64 u; float2 f; };

// Packed fp32x2 FMA (Blackwell FFMA2) — exact fp32, 2x FFMA throughput.
__device__ __forceinline__ u64 fma2(u64 a, u64 b, u64 c) {
    u64 d;
    asm("fma.rn.f32x2 %0, %1, %2, %3;" : "=l"(d) : "l"(a), "l"(b), "l"(c));
    return d;
}

// 16-byte async global->shared copy (LDGSTS).
__device__ __forceinline__ void cp_async16(u32 smem_addr, const void* gptr) {
    asm volatile("cp.async.cg.shared.global [%0], [%1], 16;"
                 :: "r"(smem_addr), "l"(gptr));
}
__device__ __forceinline__ void cp_async_commit() {
    asm volatile("cp.async.commit_group;");
}
__device__ __forceinline__ void cp_async_wait_all() {
    asm volatile("cp.async.wait_group 0;");
}

// ---- QK^T for one 32-row tile (called by tid<128). 4 t-rows x 4 j-cols per
// thread; K rows swizzled -> conflict-free.
__device__ __forceinline__ void qk_half(const float* __restrict__ Qs,
                                        const float* __restrict__ Ks,
                                        float* __restrict__ Pdst, int tid)
{
    const int jg = tid & 7;
    const int tg = (tid >> 3) & 7;              // rows 4*tg .. 4*tg+3
    const int jh = tid >> 6;                    // j half: 0 or 1
    const float* qb = Qs + (size_t)(tg * 4) * QS_STRIDE;
    // K rows jh*32+jg+8m: (row & 7) == jg for all m -> same swizzle.
    const float* kb = Ks + (size_t)(jh * 32 + jg) * KS_STRIDE;
    const int sw = jg;

    u64 acc[4][4];
    #pragma unroll
    for (int i = 0; i < 4; ++i)
        #pragma unroll
        for (int c = 0; c < 4; ++c) acc[i][c] = 0ull;

    #pragma unroll 2
    for (int d4 = 0; d4 < DD / 4; ++d4) {
        const int ko = (d4 ^ sw) * 4;           // swizzled float offset
        ulonglong2 k0 = *(const ulonglong2*)(kb + 0 * 8 * KS_STRIDE + ko);
        ulonglong2 k1 = *(const ulonglong2*)(kb + 1 * 8 * KS_STRIDE + ko);
        ulonglong2 k2 = *(const ulonglong2*)(kb + 2 * 8 * KS_STRIDE + ko);
        ulonglong2 k3 = *(const ulonglong2*)(kb + 3 * 8 * KS_STRIDE + ko);
        #pragma unroll
        for (int i = 0; i < 4; ++i) {
            ulonglong2 q = *(const ulonglong2*)(qb + (size_t)i * QS_STRIDE + d4 * 4);
            acc[i][0] = fma2(q.x, k0.x, acc[i][0]);
            acc[i][0] = fma2(q.y, k0.y, acc[i][0]);
            acc[i][1] = fma2(q.x, k1.x, acc[i][1]);
            acc[i][1] = fma2(q.y, k1.y, acc[i][1]);
            acc[i][2] = fma2(q.x, k2.x, acc[i][2]);
            acc[i][2] = fma2(q.y, k2.y, acc[i][2]);
            acc[i][3] = fma2(q.x, k3.x, acc[i][3]);
            acc[i][3] = fma2(q.y, k3.y, acc[i][3]);
        }
    }
    #pragma unroll
    for (int i = 0; i < 4; ++i)
        #pragma unroll
        for (int c = 0; c < 4; ++c) {
            UF2 u; u.u = acc[i][c];
            Pdst[(tg * 4 + i) * PS_STRIDE + jh * 32 + jg + 8 * c] =
                (u.f.x + u.f.y) * 0.0625f;      // * rsqrt(256)
        }
}

// ---- softmax + argmax over one 32-row tile (all 256 threads; 8 warps x 4
// rows in parallel, 8 lanes per row).
__device__ __forceinline__ void softmax_half(float* __restrict__ Pbase,
                                             float* __restrict__ Mdst,
                                             int tid, int prev)
{
    const int lane = tid & 31;
    const int w    = tid >> 5;            // 8 warps
    const int sub  = lane >> 3;           // row within warp group
    const int li   = lane & 7;            // 8-col chunk
    const int r    = w * 4 + sub;         // 0..31
    float* prow = Pbase + r * PS_STRIDE + li * 8;
    float4 a = *(const float4*)(prow);
    float4 c = *(const float4*)(prow + 4);
    float v[8] = {a.x, a.y, a.z, a.w, c.x, c.y, c.z, c.w};

    float bv = v[0]; int bi = li * 8;
    #pragma unroll
    for (int t = 1; t < 8; ++t)
        if (v[t] > bv) { bv = v[t]; bi = li * 8 + t; }   // strict > = first max
    #pragma unroll
    for (int off = 1; off < 8; off <<= 1) {
        float ov = __shfl_xor_sync(0xffffffffu, bv, off);
        int   oi = __shfl_xor_sync(0xffffffffu, bi, off);
        if (ov > bv || (ov == bv && oi < bi)) { bv = ov; bi = oi; }
    }
    float e[8]; float s = 0.f;
    #pragma unroll
    for (int t = 0; t < 8; ++t) { e[t] = __expf(v[t] - bv); s += e[t]; }
    #pragma unroll
    for (int off = 1; off < 8; off <<= 1)
        s += __shfl_xor_sync(0xffffffffu, s, off);
    float inv = 1.0f / s;
    *(float4*)(prow)     = make_float4(e[0] * inv, e[1] * inv, e[2] * inv, e[3] * inv);
    *(float4*)(prow + 4) = make_float4(e[4] * inv, e[5] * inv, e[6] * inv, e[7] * inv);
    if (li == 0)
        Mdst[r] = (float)(prev + bi);
}

__global__ __launch_bounds__(256, 2)
void attn_win_kernel(const float* __restrict__ Q,
                     const float* __restrict__ K,
                     const float* __restrict__ V,
                     const int*   __restrict__ prev_words,
                     float* __restrict__ out)
{
    extern __shared__ float smem[];
    float* Qs = smem + QS_OFF;
    float* Ks = smem + KS_OFF;   // K window during QK, then reused for V window
    float* Ps = smem + PS_OFF;

    const int tid = threadIdx.x;
    const int b   = blockIdx.y;
    const int t0  = blockIdx.x * 64;         // this CTA: t-rows t0 .. t0+63

    // dtype sniff: int64 (little-endian, values < 2^31) has zero high words.
    int odd_or = prev_words[1] | prev_words[3] | prev_words[5] | prev_words[7] |
                 prev_words[9] | prev_words[11] | prev_words[13] | prev_words[15];
    const int prev = (odd_or == 0) ? prev_words[2 * b] : prev_words[b];

    float* Rout = out;                       // (B,T,512)
    float* Aout = out + R_ELEMS;             // (B,N,T)
    float* Mout = Aout + AL_ELEMS;           // (B,T)

    // ===== P0: K window -> smem (swizzled) + Q_A stage (+R write) ============
    {
        const char* Kg = (const char*)(K + ((size_t)b * NK + prev) * DD);
        #pragma unroll
        for (int it = 0; it < 16; ++it) {
            int idx = tid + it * 256;
            int j   = idx >> 6;
            int d4  = idx & 63;
            u32 dst = (u32)__cvta_generic_to_shared(
                Ks + j * KS_STRIDE + (d4 ^ (j & 7)) * 4);
            cp_async16(dst, Kg + (size_t)(j * 64 + d4) * 16);
        }
        cp_async_commit();
    }
    {
        const float4* Qg = (const float4*)(Q + ((size_t)b * TT + t0) * DD);
        #pragma unroll
        for (int it = 0; it < 8; ++it) {
            int idx = tid + it * 256;
            int t   = idx >> 6;
            int d4  = idx & 63;
            float4 q4 = __ldg(&Qg[t * 64 + d4]);
            *(float4*)(Qs + t * QS_STRIDE + d4 * 4) = q4;
            __stcs((float4*)(Rout + ((size_t)b * TT + t0 + t) * (2 * DD) + DD + d4 * 4), q4);
        }
    }
    cp_async_wait_all();
    __syncthreads();                         // barrier 1

    // ===== P1: QK_A  ||  zero-fill first half ================================
    if (tid < 128) {
        qk_half(Qs, Ks, Ps, tid);
    } else {
        const int t2   = tid - 128;
        const int c16  = t2 & 15;            // float4 col 0..15
        const int rown = t2 >> 4;            // 0..7
        float* base = Aout + (size_t)b * NK * TT + t0 + 4 * c16;
        const float4 z = make_float4(0.f, 0.f, 0.f, 0.f);
        #pragma unroll 4
        for (int pass = 0; pass < 64; ++pass) {
            int n = pass * 8 + rown;         // n 0..511
            if ((unsigned)(n - prev) >= WIN)
                __stcs((float4*)(base + (size_t)n * TT), z);
        }
    }
    __syncthreads();                         // barrier 2

    // ===== P2: Q_B stage (+R write), all threads =============================
    {
        const float4* Qg = (const float4*)(Q + ((size_t)b * TT + t0 + 32) * DD);
        #pragma unroll
        for (int it = 0; it < 8; ++it) {
            int idx = tid + it * 256;
            int t   = idx >> 6;
            int d4  = idx & 63;
            float4 q4 = __ldg(&Qg[t * 64 + d4]);
            *(float4*)(Qs + t * QS_STRIDE + d4 * 4) = q4;
            __stcs((float4*)(Rout + ((size_t)b * TT + t0 + 32 + t) * (2 * DD) + DD + d4 * 4), q4);
        }
    }
    __syncthreads();                         // barrier 3

    // ===== P3: QK_B  ||  zero-fill second half ===============================
    if (tid < 128) {
        qk_half(Qs, Ks, Ps + 32 * PS_STRIDE, tid);
    } else {
        const int t2   = tid - 128;
        const int c16  = t2 & 15;
        const int rown = t2 >> 4;
        float* base = Aout + (size_t)b * NK * TT + t0 + 4 * c16;
        const float4 z = make_float4(0.f, 0.f, 0.f, 0.f);
        #pragma unroll 4
        for (int pass = 64; pass < 128; ++pass) {
            int n = pass * 8 + rown;         // n 512..1023
            if ((unsigned)(n - prev) >= WIN)
                __stcs((float4*)(base + (size_t)n * TT), z);
        }
    }
    __syncthreads();                         // barrier 4 (K dead)

    // ===== P4: V window -> smem (swizzled) + softmax A & B ===================
    {
        const char* Vg = (const char*)(V + ((size_t)b * NK + prev) * DD);
        #pragma unroll
        for (int it = 0; it < 16; ++it) {
            int idx = tid + it * 256;
            int j   = idx >> 6;
            int d4  = idx & 63;
            u32 dst = (u32)__cvta_generic_to_shared(
                Ks + j * KS_STRIDE + (d4 ^ (j & 7)) * 4);
            cp_async16(dst, Vg + (size_t)(j * 64 + d4) * 16);
        }
        cp_async_commit();
    }
    softmax_half(Ps,                  Mout + (size_t)b * TT + t0,      tid, prev);
    softmax_half(Ps + 32 * PS_STRIDE, Mout + (size_t)b * TT + t0 + 32, tid, prev);
    cp_async_wait_all();
    __syncthreads();                         // barrier 5 (probs + V visible)

    // ===== P5: scatter A+B + AV (single pass, all 64 rows) ===================
    {   // scatter: 64 j-rows x 16 float4 t-cols = 1024 items, 4/thread
        #pragma unroll
        for (int it = 0; it < 4; ++it) {
            int item = tid + it * 256;
            int j    = item >> 4;            // 0..63
            int c16  = item & 15;            // float4 col 0..15 (64 t-cols)
            float4 v;
            v.x = Ps[(4 * c16 + 0) * PS_STRIDE + j];
            v.y = Ps[(4 * c16 + 1) * PS_STRIDE + j];
            v.z = Ps[(4 * c16 + 2) * PS_STRIDE + j];
            v.w = Ps[(4 * c16 + 3) * PS_STRIDE + j];
            __stcs((float4*)(Aout + ((size_t)b * NK + prev + j) * TT + t0 + 4 * c16), v);
        }
    }
    {   // AV: thread owns 8 t-rows x 8 d-floats (chunks 2*d16, 2*d16+1).
        // Per j4-iter: 8 V + 8 P LDS.128 feed 128 FFMA2 (2 B/FFMA2).
        const int d16 = tid & 31;            // d-float group: floats 8*d16..+7
        const int tg  = tid >> 5;            // warp 0..7 -> rows 8*tg..+7
        const int c0  = 2 * d16;             // first 16B chunk index
        u64 acc[8][4];
        #pragma unroll
        for (int r = 0; r < 8; ++r)
            #pragma unroll
            for (int c = 0; c < 4; ++c) acc[r][c] = 0ull;

        const float* Pb = Ps + (size_t)(tg * 8) * PS_STRIDE;

        #pragma unroll 1
        for (int j4 = 0; j4 < WIN / 4; ++j4) {
            ulonglong2 v0[4], v1[4];
            #pragma unroll
            for (int jj = 0; jj < 4; ++jj) {
                int row = j4 * 4 + jj;
                int s   = row & 7;
                const float* rb = Ks + (size_t)row * KS_STRIDE;
                v0[jj] = *(const ulonglong2*)(rb + ((c0)     ^ s) * 4);
                v1[jj] = *(const ulonglong2*)(rb + ((c0 + 1) ^ s) * 4);
            }
            #pragma unroll
            for (int r = 0; r < 8; ++r) {
                float4 p4 = *(const float4*)(Pb + r * PS_STRIDE + j4 * 4);
                UF2 pp;
                pp.f = make_float2(p4.x, p4.x);
                acc[r][0] = fma2(pp.u, v0[0].x, acc[r][0]);
                acc[r][1] = fma2(pp.u, v0[0].y, acc[r][1]);
                acc[r][2] = fma2(pp.u, v1[0].x, acc[r][2]);
                acc[r][3] = fma2(pp.u, v1[0].y, acc[r][3]);
                pp.f = make_float2(p4.y, p4.y);
                acc[r][0] = fma2(pp.u, v0[1].x, acc[r][0]);
                acc[r][1] = fma2(pp.u, v0[1].y, acc[r][1]);
                acc[r][2] = fma2(pp.u, v1[1].x, acc[r][2]);
                acc[r][3] = fma2(pp.u, v1[1].y, acc[r][3]);
                pp.f = make_float2(p4.z, p4.z);
                acc[r][0] = fma2(pp.u, v0[2].x, acc[r][0]);
                acc[r][1] = fma2(pp.u, v0[2].y, acc[r][1]);
                acc[r][2] = fma2(pp.u, v1[2].x, acc[r][2]);
                acc[r][3] = fma2(pp.u, v1[2].y, acc[r][3]);
                pp.f = make_float2(p4.w, p4.w);
                acc[r][0] = fma2(pp.u, v0[3].x, acc[r][0]);
                acc[r][1] = fma2(pp.u, v0[3].y, acc[r][1]);
                acc[r][2] = fma2(pp.u, v1[3].x, acc[r][2]);
                acc[r][3] = fma2(pp.u, v1[3].y, acc[r][3]);
            }
        }
        #pragma unroll
        for (int r = 0; r < 8; ++r) {
            float* dst = Rout + ((size_t)b * TT + t0 + tg * 8 + r) * (2 * DD) + 8 * d16;
            float4 o0, o1;
            o0.x = ((UF2*)&acc[r][0])->f.x;  o0.y = ((UF2*)&acc[r][0])->f.y;
            o0.z = ((UF2*)&acc[r][1])->f.x;  o0.w = ((UF2*)&acc[r][1])->f.y;
            o1.x = ((UF2*)&acc[r][2])->f.x;  o1.y = ((UF2*)&acc[r][2])->f.y;
            o1.z = ((UF2*)&acc[r][3])->f.x;  o1.w = ((UF2*)&acc[r][3])->f.y;
            __stcs((float4*)dst,     o0);
            __stcs((float4*)dst + 1, o1);
        }
    }
}

extern "C" void kernel_launch(void* const* d_in, const int* in_sizes, int n_in,
                              void* d_out, int out_size)
{
    const float* Q  = (const float*)d_in[0];
    const float* K  = (const float*)d_in[1];
    const float* V  = (const float*)d_in[2];
    const int* prevw = (const int*)d_in[3];   // int64 or int32, sniffed in-kernel
    float* out = (float*)d_out;

    cudaFuncSetAttribute(attn_win_kernel,
                         cudaFuncAttributeMaxDynamicSharedMemorySize, SMEM_BYTES);

    dim3 grid(TT / 64, BB);                   // 256 CTAs -> single wave at occ 2
    attn_win_kernel<<<grid, 256, SMEM_BYTES, 0>>>(Q, K, V, prevw, out);
}